// round 8
// baseline (speedup 1.0000x reference)
#include <cuda_runtime.h>
#include <cuda_bf16.h>
#include <math.h>

#define NPROP 2000
#define NGT   100
#define TR    200
#define PM    66      // POS_MAX = int(200*0.33)
#define HH    512
#define WW    512
#define MS    28
#define NB    148     // one block per SM, single wave
#define BT    1024

// inter-block state (no allocs allowed -> device globals; overwrite-or-reset only)
__device__ unsigned g_info[2][2048];   // per-proposal: asg<<2 | pb<<1 | nb  (e>=2000 never written: stays 0)
__device__ int      g_done;            // arrival counter (reset by last passer)
__device__ int      g_mdone;           // wait-passed counter (reset by last passer)
__device__ unsigned g_maskflags;       // OR-accumulated dtype probe (idempotent)

__device__ __forceinline__ float cvtf(float v)          { return v; }
__device__ __forceinline__ float cvtf(int v)            { return (float)v; }
__device__ __forceinline__ float cvtf(unsigned char v)  { return (float)v; }
__device__ __forceinline__ float cvtf(__nv_bfloat16 v)  { return __bfloat162float(v); }

// first word with inclusive-cum > r, then select r-th set bit position
__device__ __forceinline__ int select_idx(const int* cum, const unsigned* bits, int r) {
    int lo = 0, hi = 63;
    while (lo < hi) { int mid = (lo + hi) >> 1; if (cum[mid] > r) hi = mid; else lo = mid + 1; }
    int prev = lo ? cum[lo - 1] : 0;
    unsigned w = bits[lo];
    int rr = r - prev;
    while (rr--) w &= w - 1;
    return (lo << 5) + __ffs(w) - 1;
}

// ---------------------------------------------------------------------------
// Persistent single-wave kernel, 148 blocks x 1024 threads (1 block/SM):
//   1. classify: warp task q = bid + 148*wid (q<4000): batch q/2000, prop q%2000
//   2. global barrier (148 arrivals, overlapped reset)
//   3. per-block self-finalize: ballots + scans over g_info (both batches)
//   4. balanced gather: half-rows h = bid, bid+148 (264 total)
//      + row ownership r = bid, bid+148, bid+296 for rois/class/deltas/zeroing
// ---------------------------------------------------------------------------
__global__ __launch_bounds__(BT, 1) void dtl_fused(
    const float* __restrict__ props,
    const int*   __restrict__ cls,
    const float* __restrict__ gtb,
    const void*  __restrict__ masks,
    float*       __restrict__ out)
{
    const int tid = threadIdx.x;
    const int bid = blockIdx.x;
    const int wid = tid >> 5;
    const int lane = tid & 31;

    __shared__ float         s_gt[2][NGT][5];     // pad 5: conflict-free strided reads
    __shared__ int           s_cls[2][NGT];
    __shared__ unsigned char s_fg[2][NGT], s_crowd[2][NGT];
    __shared__ unsigned      s_pw[2][64], s_nw[2][64];
    __shared__ int           s_cum[4][64];        // [2b + (0=pos,1=neg)] inclusive
    __shared__ int           s_tot[4];
    __shared__ int           s_Np[2], s_Nn[2];
    __shared__ int           s_hg[2], s_hq[2], s_hb[2], s_hj[2], s_hvalid[2];
    __shared__ float         s_hbox[2][4];
    __shared__ int           s_go;

    // ---- load gt boxes/classes for BOTH batches (float4) ----
    if (tid < 2 * NGT) {
        int bt = tid / NGT, gi = tid - bt * NGT;
        float4 gv = ((const float4*)gtb)[bt * NGT + gi];
        s_gt[bt][gi][0] = gv.x; s_gt[bt][gi][1] = gv.y;
        s_gt[bt][gi][2] = gv.z; s_gt[bt][gi][3] = gv.w;
        bool vg = (fabsf(gv.x)+fabsf(gv.y)+fabsf(gv.z)+fabsf(gv.w)) > 0.0f;
        int c = cls[bt * NGT + gi];
        s_cls[bt][gi]   = c;
        s_fg[bt][gi]    = (vg && c > 0) ? 1 : 0;
        s_crowd[bt][gi] = (vg && c < 0) ? 1 : 0;
    }

    // ---- dtype probe: block 0, warps 28..31 (idle in classify) ----
    if (bid == 0 && tid >= 896) {
        const unsigned* maskw = (const unsigned*)masks;
        unsigned local = 0u;
        int t0 = tid - 896;
        #pragma unroll
        for (int it = 0; it < 16; it++) {
            unsigned v = maskw[t0 + it * 128];
            if (v == 0u || v == 1u) continue;                        // i32-compatible
            else if (v == 0x3F803F80u || v == 0x00003F80u) local |= 4u;  // bf16 pair
            else if (v == 0x3F800000u)                     local |= 2u;  // f32 1.0
            else if ((v & ~0x01010101u) == 0u)             local |= 1u;  // u8 bytes
        }
        local = __reduce_or_sync(0xffffffffu, local);
        if (lane == 0 && local) atomicOr(&g_maskflags, local);
    }
    __syncthreads();

    // ---- classify: warp task q = bid + 148*wid ----
    {
        const int q = bid + NB * wid;
        if (q < 2 * NPROP) {
            const int cb = (q >= NPROP) ? 1 : 0;
            const int n  = q - cb * NPROP;
            const float4 pv = ((const float4*)props)[cb * NPROP + n];
            const float p0 = pv.x, p1 = pv.y, p2 = pv.z, p3 = pv.w;
            const bool vp = (fabsf(p0)+fabsf(p1)+fabsf(p2)+fabsf(p3)) > 0.0f;
            const float a1 = (p2 - p0) * (p3 - p1);
            float fgmax = 0.0f, crmax = 0.0f, best = -1e30f;
            int bi = 0;
            #pragma unroll
            for (int t = 0; t < 4; t++) {
                int g = lane + t * 32;
                if (g < NGT) {
                    float q0 = s_gt[cb][g][0], q1 = s_gt[cb][g][1];
                    float q2 = s_gt[cb][g][2], q3 = s_gt[cb][g][3];
                    float y1 = fmaxf(p0, q0);
                    float x1 = fmaxf(p1, q1);
                    float y2 = fminf(p2, q2);
                    float x2 = fminf(p3, q3);
                    float inter = fmaxf(x2 - x1, 0.0f) * fmaxf(y2 - y1, 0.0f);
                    float a2 = (q2 - q0) * (q3 - q1);
                    float un = a1 + a2 - inter;
                    float iou = (un > 0.0f) ? (inter / un) : 0.0f;
                    if (!vp) iou = 0.0f;
                    if (s_crowd[cb][g] && iou > crmax) crmax = iou;
                    float fv = s_fg[cb][g] ? iou : 0.0f;
                    if (fv > fgmax) fgmax = fv;
                    float av = s_fg[cb][g] ? iou : -1.0f;
                    if (av > best) { best = av; bi = g; }   // ascending g: keeps first max
                }
            }
            #pragma unroll
            for (int off = 16; off; off >>= 1) {
                fgmax = fmaxf(fgmax, __shfl_xor_sync(0xffffffffu, fgmax, off));
                crmax = fmaxf(crmax, __shfl_xor_sync(0xffffffffu, crmax, off));
                float ob = __shfl_xor_sync(0xffffffffu, best, off);
                int   og = __shfl_xor_sync(0xffffffffu, bi,   off);
                if (ob > best || (ob == best && og < bi)) { best = ob; bi = og; }
            }
            if (lane == 0) {
                unsigned pb = ((fgmax >= 0.5f) && vp) ? 1u : 0u;
                unsigned nb = ((fgmax <  0.5f) && (crmax < 0.001f) && vp) ? 1u : 0u;
                g_info[cb][n] = ((unsigned)bi << 2) | (pb << 1) | nb;
            }
        }
    }
    __threadfence();
    __syncthreads();

    // ---- global barrier (148 arrivals) ----
    if (tid == 0) {
        atomicAdd(&g_done, 1);
        while (*((volatile int*)&g_done) < NB) __nanosleep(64);
        __threadfence();   // acquire
        s_go = 1;
    }
    __syncthreads();
    (void)s_go;
    // overlapped reset (last passer resets both counters)
    if (tid == 0) {
        int c = atomicAdd(&g_mdone, 1);
        if (c == NB - 1) { g_done = 0; g_mdone = 0; __threadfence(); }
    }

    // ---- ballots over g_info (both batches; entries >=2000 are 0) ----
    #pragma unroll
    for (int b2 = 0; b2 < 2; b2++) {
        #pragma unroll
        for (int h = 0; h < 2; h++) {
            unsigned info = g_info[b2][tid + h * 1024];
            unsigned pm = __ballot_sync(0xffffffffu, info & 2u);
            unsigned nm = __ballot_sync(0xffffffffu, info & 1u);
            if (lane == 0) { s_pw[b2][wid + h * 32] = pm; s_nw[b2][wid + h * 32] = nm; }
        }
    }
    __syncthreads();

    // ---- scans: warps 0..3 = {b0 pos, b0 neg, b1 pos, b1 neg} ----
    if (wid < 4) {
        int b2 = wid >> 1;
        const unsigned* src = (wid & 1) ? s_nw[b2] : s_pw[b2];
        int a = __popc(src[lane]);
        int c = __popc(src[lane + 32]);
        int ia = a, ic = c;
        #pragma unroll
        for (int off = 1; off < 32; off <<= 1) {
            int t0 = __shfl_up_sync(0xffffffffu, ia, off);
            int t1 = __shfl_up_sync(0xffffffffu, ic, off);
            if (lane >= off) { ia += t0; ic += t1; }
        }
        int totA = __shfl_sync(0xffffffffu, ia, 31);
        s_cum[wid][lane]      = ia;            // inclusive
        s_cum[wid][lane + 32] = totA + ic;
        if (lane == 31) s_tot[wid] = totA + ic;
    }
    __syncthreads();
    if (tid < 2) {
        int Np = min(s_tot[2 * tid], PM);
        const float R = (float)(1.0 / 0.33);
        int want = (int)floorf(R * (float)Np) - Np;
        int Nn = min(want, s_tot[2 * tid + 1]);
        Nn = max(Nn, 0);
        s_Np[tid] = Np;
        s_Nn[tid] = min(Nn, TR - Np);
    }
    __syncthreads();

    // ---- row scalar outputs (rows r = bid + 148*t), tids 0..2 ----
    if (tid < 3) {
        int r = bid + NB * tid;
        if (r < 2 * TR) {
            int b2 = r / TR, k = r - b2 * TR;
            int Np = s_Np[b2], Nn = s_Nn[b2];
            float* ro = out + (size_t)r * 4;
            float* cl = out + 1600 + r;
            float* de = out + 2000 + (size_t)r * 4;
            if (k < Np) {
                int n = select_idx(s_cum[2 * b2], s_pw[b2], k);
                int g = (int)(g_info[b2][n] >> 2);
                float4 pv = ((const float4*)props)[b2 * NPROP + n];
                float p0 = pv.x, p1 = pv.y, p2 = pv.z, p3 = pv.w;
                ro[0] = p0; ro[1] = p1; ro[2] = p2; ro[3] = p3;
                cl[0] = (float)s_cls[b2][g];
                float h  = p2 - p0, w2 = p3 - p1;
                float cy = p0 + 0.5f * h, cx = p1 + 0.5f * w2;
                float g0 = s_gt[b2][g][0], g1 = s_gt[b2][g][1];
                float g2 = s_gt[b2][g][2], g3 = s_gt[b2][g][3];
                float gh = g2 - g0, gw = g3 - g1;
                float gcy = g0 + 0.5f * gh, gcx = g1 + 0.5f * gw;
                de[0] = ((gcy - cy) / h)  / 0.1f;
                de[1] = ((gcx - cx) / w2) / 0.1f;
                de[2] = logf(gh / h)  / 0.2f;
                de[3] = logf(gw / w2) / 0.2f;
            } else if (k < Np + Nn) {
                int n = select_idx(s_cum[2 * b2 + 1], s_nw[b2], k - Np);
                float4 pv = ((const float4*)props)[b2 * NPROP + n];
                ro[0] = pv.x; ro[1] = pv.y; ro[2] = pv.z; ro[3] = pv.w;
                cl[0] = 0.0f;
                de[0] = de[1] = de[2] = de[3] = 0.0f;
            } else {
                ro[0] = ro[1] = ro[2] = ro[3] = 0.0f;
                cl[0] = 0.0f;
                de[0] = de[1] = de[2] = de[3] = 0.0f;
            }
        }
    }

    // ---- half-row gather lookups (h = bid + 148*hh), tids 32,33 ----
    if (tid >= 32 && tid < 34) {
        int hh = tid - 32;
        int h = bid + NB * hh;
        int valid = 0;
        if (h < 4 * PM) {                       // 264 half-rows
            int b2 = (h >= 2 * PM) ? 1 : 0;
            int rem = h - b2 * 2 * PM;
            int jj = rem >> 1;
            int q  = rem & 1;
            if (jj < s_Np[b2]) {
                int n = select_idx(s_cum[2 * b2], s_pw[b2], jj);
                int g = (int)(g_info[b2][n] >> 2);
                float4 pv = ((const float4*)props)[b2 * NPROP + n];
                s_hbox[hh][0] = pv.x; s_hbox[hh][1] = pv.y;
                s_hbox[hh][2] = pv.z; s_hbox[hh][3] = pv.w;
                s_hg[hh] = g; s_hq[hh] = q; s_hb[hh] = b2; s_hj[hh] = jj;
                valid = 1;
            }
        }
        s_hvalid[hh] = valid;
    }
    __syncthreads();

    // ---- gather (tid<392: one pixel per half) + dead-row zero (tid>=392) ----
    if (tid < 392) {
        const unsigned mode = g_maskflags;
        unsigned idx[2][4];
        float    wyv[2], wxv[2];
        bool     okv[2], act[2];
        float*   dst[2];
        #pragma unroll
        for (int hh = 0; hh < 2; hh++) {
            act[hh] = s_hvalid[hh] != 0;
            int q  = act[hh] ? s_hq[hh] : 0;
            int p  = q * 392 + tid;
            int i  = p / MS, k2 = p - i * MS;
            float y1 = s_hbox[hh][0], x1 = s_hbox[hh][1];
            float y2 = s_hbox[hh][2], x2 = s_hbox[hh][3];
            float sy = ((y2 - y1) * 511.0f) / 27.0f;
            float sx = ((x2 - x1) * 511.0f) / 27.0f;
            float ys = y1 * 511.0f + (float)i  * sy;
            float xs = x1 * 511.0f + (float)k2 * sx;
            float y0f = floorf(ys), x0f = floorf(xs);
            wyv[hh] = ys - y0f; wxv[hh] = xs - x0f;
            int y0i = (int)fminf(fmaxf(y0f,        0.0f), 511.0f);
            int y1i = (int)fminf(fmaxf(y0f + 1.0f, 0.0f), 511.0f);
            int x0i = (int)fminf(fmaxf(x0f,        0.0f), 511.0f);
            int x1i = (int)fminf(fmaxf(x0f + 1.0f, 0.0f), 511.0f);
            unsigned mb = act[hh] ? (unsigned)s_hb[hh] * (HH * WW * NGT) : 0u;
            int g = act[hh] ? s_hg[hh] : 0;
            idx[hh][0] = act[hh] ? mb + (unsigned)(y0i * WW + x0i) * NGT + g : 0u;
            idx[hh][1] = act[hh] ? mb + (unsigned)(y0i * WW + x1i) * NGT + g : 0u;
            idx[hh][2] = act[hh] ? mb + (unsigned)(y1i * WW + x0i) * NGT + g : 0u;
            idx[hh][3] = act[hh] ? mb + (unsigned)(y1i * WW + x1i) * NGT + g : 0u;
            okv[hh] = (ys >= 0.0f) && (ys <= 511.0f) && (xs >= 0.0f) && (xs <= 511.0f);
            dst[hh] = out + 3600 + ((size_t)(act[hh] ? s_hb[hh] * TR + s_hj[hh] : 0)) * (MS * MS) + p;
        }
        float v[2][4];
        if (mode & 4u) {
            const __nv_bfloat16* m = (const __nv_bfloat16*)masks;
            #pragma unroll
            for (int hh = 0; hh < 2; hh++)
                #pragma unroll
                for (int q2 = 0; q2 < 4; q2++) v[hh][q2] = cvtf(m[idx[hh][q2]]);
        } else if (mode & 2u) {
            const float* m = (const float*)masks;
            #pragma unroll
            for (int hh = 0; hh < 2; hh++)
                #pragma unroll
                for (int q2 = 0; q2 < 4; q2++) v[hh][q2] = cvtf(m[idx[hh][q2]]);
        } else if (mode & 1u) {
            const unsigned char* m = (const unsigned char*)masks;
            #pragma unroll
            for (int hh = 0; hh < 2; hh++)
                #pragma unroll
                for (int q2 = 0; q2 < 4; q2++) v[hh][q2] = cvtf(m[idx[hh][q2]]);
        } else {
            const int* m = (const int*)masks;
            #pragma unroll
            for (int hh = 0; hh < 2; hh++)
                #pragma unroll
                for (int q2 = 0; q2 < 4; q2++) v[hh][q2] = cvtf(m[idx[hh][q2]]);
        }
        #pragma unroll
        for (int hh = 0; hh < 2; hh++) {
            if (!act[hh]) continue;
            float val = (v[hh][0] * (1.0f - wxv[hh]) + v[hh][1] * wxv[hh]) * (1.0f - wyv[hh])
                      + (v[hh][2] * (1.0f - wxv[hh]) + v[hh][3] * wxv[hh]) * wyv[hh];
            *dst[hh] = okv[hh] ? rintf(val) : 0.0f;   // half-even == jnp.round
        }
    } else {
        // zero dead mask rows for the rows this block owns
        #pragma unroll
        for (int t = 0; t < 3; t++) {
            int r = bid + NB * t;
            if (r < 2 * TR) {
                int b2 = r / TR, k = r - b2 * TR;
                if (k >= s_Np[b2]) {
                    float* om = out + 3600 + (size_t)r * (MS * MS);
                    for (int p = tid - 392; p < MS * MS; p += BT - 392) om[p] = 0.0f;
                }
            }
        }
    }
}

// ---------------------------------------------------------------------------
extern "C" void kernel_launch(void* const* d_in, const int* in_sizes, int n_in,
                              void* d_out, int out_size)
{
    const float* props = (const float*)d_in[0];
    const int*   cls   = (const int*)  d_in[1];
    const float* gtb   = (const float*)d_in[2];
    const void*  masks = d_in[3];
    float* out = (float*)d_out;

    dtl_fused<<<NB, BT>>>(props, cls, gtb, masks, out);
}

// round 9
// speedup vs baseline: 1.0171x; 1.0171x over previous
#include <cuda_runtime.h>
#include <cuda_bf16.h>
#include <math.h>

#define NPROP 2000
#define NGT   100
#define TR    200
#define PM    66      // POS_MAX = int(200*0.33)
#define HH    512
#define WW    512
#define MS    28
#define PIX   (MS * MS)           // 784
#define BT    512                 // threads per block
#define PWPB  10                  // proposals (classify warps) per block
#define BPB   200                 // blocks per batch (= TR; each owns one output row)
#define NBLK  (2 * BPB)           // 400

// inter-block state (no allocs allowed -> device globals; overwrite-or-reset only)
__device__ unsigned g_info[2][2048];      // per-proposal: asg<<2 | pb<<1 | nb
__device__ unsigned g_blockbits[2][BPB];  // per classify block: posbits | negbits<<10
__device__ int      g_done[2];            // classify-done counter (reset by 200th waiter)
__device__ int      g_mdone[2];           // wait-passed counter  (reset by 200th waiter)
__device__ unsigned g_maskflags;          // OR-accumulated dtype probe (idempotent)

__device__ __forceinline__ float cvtf(float v)          { return v; }
__device__ __forceinline__ float cvtf(int v)            { return (float)v; }
__device__ __forceinline__ float cvtf(unsigned char v)  { return (float)v; }
__device__ __forceinline__ float cvtf(__nv_bfloat16 v)  { return __bfloat162float(v); }

// r-th (0-based) selected proposal from 200 summary words with inclusive cums.
// pos: low 10 bits, neg: high 10 bits.
__device__ __forceinline__ int sel200(const int* cum, const unsigned* bits, int r, int neg) {
    int lo = 0, hi = BPB - 1;
    while (lo < hi) { int mid = (lo + hi) >> 1; if (cum[mid] > r) hi = mid; else lo = mid + 1; }
    int prev = lo ? cum[lo - 1] : 0;
    unsigned w = neg ? (bits[lo] >> 10) : (bits[lo] & 0x3FFu);
    int rr = r - prev;
    while (rr--) w &= w - 1;
    return lo * PWPB + __ffs(w) - 1;
}

// ---------------------------------------------------------------------------
// 400 blocks x 512 (single wave). R7 skeleton + balanced chunked gather:
//  1. classify 10 proposals/block (warp-per-proposal), publish summary word
//  2. per-batch barrier (200 arrivals, tid0-fence release, overlapped reset)
//  3. light self-finalize: 200 summary words -> scans -> Np/Nn
//  4. block k gathers contiguous pixel chunk [k*T/200,(k+1)*T/200), T=Np*784
//     (<=259 px, <=2 rows => 2 selects); row-k scalars + dead-row zero overlap
// ---------------------------------------------------------------------------
__global__ __launch_bounds__(BT, 3) void dtl_fused(
    const float* __restrict__ props,
    const int*   __restrict__ cls,
    const float* __restrict__ gtb,
    const void*  __restrict__ masks,
    float*       __restrict__ out)
{
    const int tid = threadIdx.x;
    const int b   = blockIdx.x / BPB;        // batch
    const int k   = blockIdx.x % BPB;        // block-in-batch == output row
    const int wid  = tid >> 5;
    const int lane = tid & 31;

    __shared__ float         s_gt[NGT][5];   // pad 5: conflict-free strided reads
    __shared__ int           s_cls[NGT];
    __shared__ unsigned char s_fg[NGT], s_crowd[NGT];
    __shared__ unsigned char s_p10[PWPB], s_n10[PWPB];
    __shared__ unsigned      s_bits[224];
    __shared__ int           s_cumP[224], s_cumN[224];
    __shared__ int           s_wtP[8], s_wtN[8];
    __shared__ int           s_Np, s_Nn;
    __shared__ int           s_rowg[2];
    __shared__ float         s_rbox[2][4];
    __shared__ int           s_go;

    const float* P = props + (size_t)b * NPROP * 4;
    const float* G = gtb   + (size_t)b * NGT * 4;
    const int*   C = cls   + (size_t)b * NGT;

    if (tid < NGT) {
        float4 gv = ((const float4*)G)[tid];
        s_gt[tid][0] = gv.x; s_gt[tid][1] = gv.y; s_gt[tid][2] = gv.z; s_gt[tid][3] = gv.w;
        bool vg = (fabsf(gv.x)+fabsf(gv.y)+fabsf(gv.z)+fabsf(gv.w)) > 0.0f;
        int c = C[tid];
        s_cls[tid]   = c;
        s_fg[tid]    = (vg && c > 0) ? 1 : 0;
        s_crowd[tid] = (vg && c < 0) ? 1 : 0;
    }

    // dtype probe on classify-idle warps 10..13 of block 0 (zero skew)
    if (blockIdx.x == 0 && wid >= 10 && wid < 14) {
        const unsigned* maskw = (const unsigned*)masks;
        int t0 = (wid - 10) * 32 + lane;       // 0..127
        unsigned local = 0u;
        #pragma unroll
        for (int it = 0; it < 16; it++) {
            unsigned v = maskw[t0 + it * 128];
            if (v == 0u || v == 1u) continue;                        // i32-compatible
            else if (v == 0x3F803F80u || v == 0x00003F80u) local |= 4u;  // bf16 pair
            else if (v == 0x3F800000u)                     local |= 2u;  // f32 1.0
            else if ((v & ~0x01010101u) == 0u)             local |= 1u;  // u8 bytes
        }
        local = __reduce_or_sync(0xffffffffu, local);
        if (lane == 0 && local) atomicOr(&g_maskflags, local);
    }
    __syncthreads();

    // ---- classify: warps 0..9 each take one proposal, lanes split the GTs ----
    if (wid < PWPB) {
        const int n = k * PWPB + wid;
        const float4 pv = ((const float4*)P)[n];        // broadcast within warp
        const float p0 = pv.x, p1 = pv.y, p2 = pv.z, p3 = pv.w;
        const bool vp = (fabsf(p0)+fabsf(p1)+fabsf(p2)+fabsf(p3)) > 0.0f;
        const float a1 = (p2 - p0) * (p3 - p1);
        float fgmax = 0.0f, crmax = 0.0f, best = -1e30f;
        int bi = 0;
        #pragma unroll
        for (int t = 0; t < 4; t++) {
            int g = lane + t * 32;
            if (g < NGT) {
                float q0 = s_gt[g][0], q1 = s_gt[g][1], q2 = s_gt[g][2], q3 = s_gt[g][3];
                float y1 = fmaxf(p0, q0);
                float x1 = fmaxf(p1, q1);
                float y2 = fminf(p2, q2);
                float x2 = fminf(p3, q3);
                float inter = fmaxf(x2 - x1, 0.0f) * fmaxf(y2 - y1, 0.0f);
                float a2 = (q2 - q0) * (q3 - q1);
                float un = a1 + a2 - inter;
                float iou = (un > 0.0f) ? (inter / un) : 0.0f;
                if (!vp) iou = 0.0f;
                if (s_crowd[g] && iou > crmax) crmax = iou;
                float fv = s_fg[g] ? iou : 0.0f;
                if (fv > fgmax) fgmax = fv;
                float av = s_fg[g] ? iou : -1.0f;
                if (av > best) { best = av; bi = g; }   // ascending g: keeps first max
            }
        }
        #pragma unroll
        for (int off = 16; off; off >>= 1) {
            fgmax = fmaxf(fgmax, __shfl_xor_sync(0xffffffffu, fgmax, off));
            crmax = fmaxf(crmax, __shfl_xor_sync(0xffffffffu, crmax, off));
            float ob = __shfl_xor_sync(0xffffffffu, best, off);
            int   og = __shfl_xor_sync(0xffffffffu, bi,   off);
            if (ob > best || (ob == best && og < bi)) { best = ob; bi = og; }
        }
        if (lane == 0) {
            unsigned pb = ((fgmax >= 0.5f) && vp) ? 1u : 0u;
            unsigned nb = ((fgmax <  0.5f) && (crmax < 0.001f) && vp) ? 1u : 0u;
            g_info[b][n] = ((unsigned)bi << 2) | (pb << 1) | nb;
            s_p10[wid] = (unsigned char)pb;
            s_n10[wid] = (unsigned char)nb;
        }
    }
    __syncthreads();

    // ---- barrier: cg-style release (tid0-only fence), per-batch 200 arrivals ----
    if (tid == 0) {
        unsigned w = 0u;
        #pragma unroll
        for (int i = 0; i < PWPB; i++)
            w |= ((unsigned)s_p10[i] << i) | ((unsigned)s_n10[i] << (10 + i));
        g_blockbits[b][k] = w;
        __threadfence();                       // release g_info + blockbits
        atomicAdd(&g_done[b], 1);
        while (*((volatile int*)&g_done[b]) < BPB) __nanosleep(64);
        __threadfence();                       // acquire
        s_go = 1;
    }
    __syncthreads();
    (void)s_go;
    // overlapped reset (200th passer resets)
    if (tid == 0) {
        int c = atomicAdd(&g_mdone[b], 1);
        if (c == BPB - 1) { g_done[b] = 0; g_mdone[b] = 0; __threadfence(); }
    }

    // ---- light self-finalize: scan 200 summary words ----
    unsigned wbits = 0u; int pcnt = 0, ncnt = 0;
    if (tid < BPB) {
        wbits = g_blockbits[b][tid];
        pcnt = __popc(wbits & 0x3FFu);
        ncnt = __popc(wbits >> 10);
    }
    if (tid < 224) s_bits[tid] = wbits;
    int ip = pcnt, in_ = ncnt;
    if (wid < 7) {
        #pragma unroll
        for (int off = 1; off < 32; off <<= 1) {
            int a = __shfl_up_sync(0xffffffffu, ip,  off);
            int c = __shfl_up_sync(0xffffffffu, in_, off);
            if (lane >= off) { ip += a; in_ += c; }
        }
        if (lane == 31) { s_wtP[wid] = ip; s_wtN[wid] = in_; }
    }
    __syncthreads();
    if (tid == 0) {
        int rp = 0, rn = 0;
        #pragma unroll
        for (int i = 0; i < 7; i++) {
            int a = s_wtP[i], c = s_wtN[i];
            s_wtP[i] = rp; s_wtN[i] = rn;
            rp += a; rn += c;
        }
        int Np = min(rp, PM);
        const float R = (float)(1.0 / 0.33);
        int want = (int)floorf(R * (float)Np) - Np;
        int Nn = min(want, rn);
        Nn = max(Nn, 0);
        s_Np = Np;
        s_Nn = min(Nn, TR - Np);
    }
    __syncthreads();
    if (tid < BPB && wid < 7) {
        s_cumP[tid] = ip  + s_wtP[wid];        // inclusive
        s_cumN[tid] = in_ + s_wtN[wid];
    }
    __syncthreads();

    const int Np = s_Np, Nn = s_Nn;
    const int T    = Np * PIX;                 // total live pixels this batch
    const int base = (int)(((long long)k * T) / BPB);
    const int endp = (int)(((long long)(k + 1) * T) / BPB);
    const int len  = endp - base;              // <= 259 < BT
    const int r0   = (len > 0) ? (base / PIX) : 0;

    // row info for the (<=2) rows this chunk touches
    if (tid < 2 && len > 0) {
        int rr = (tid == 0) ? r0 : (endp - 1) / PIX;
        if (tid == 0 || rr != r0) {
            int n = sel200(s_cumP, s_bits, rr, 0);
            int g = (int)(g_info[b][n] >> 2);
            float4 pv = ((const float4*)P)[n];
            s_rbox[tid][0] = pv.x; s_rbox[tid][1] = pv.y;
            s_rbox[tid][2] = pv.z; s_rbox[tid][3] = pv.w;
            s_rowg[tid] = g;
        }
    }
    __syncthreads();

    // ---- gather: one pixel per thread over this block's chunk ----
    if (tid < len) {
        const int p  = base + tid;
        const int j  = p / PIX;
        const int pp = p - j * PIX;
        const int slot = (j != r0) ? 1 : 0;
        const float y1 = s_rbox[slot][0], x1 = s_rbox[slot][1];
        const float y2 = s_rbox[slot][2], x2 = s_rbox[slot][3];
        const int   g  = s_rowg[slot];
        const float sy = ((y2 - y1) * 511.0f) / 27.0f;
        const float sx = ((x2 - x1) * 511.0f) / 27.0f;
        const int i  = pp / MS, kx = pp - i * MS;
        const float ys = y1 * 511.0f + (float)i  * sy;
        const float xs = x1 * 511.0f + (float)kx * sx;
        const float y0f = floorf(ys), x0f = floorf(xs);
        const float wy = ys - y0f, wx = xs - x0f;
        const int y0i = (int)fminf(fmaxf(y0f,        0.0f), 511.0f);
        const int y1i = (int)fminf(fmaxf(y0f + 1.0f, 0.0f), 511.0f);
        const int x0i = (int)fminf(fmaxf(x0f,        0.0f), 511.0f);
        const int x1i = (int)fminf(fmaxf(x0f + 1.0f, 0.0f), 511.0f);
        const unsigned mb = (unsigned)b * (HH * WW * NGT);
        const unsigned i00 = mb + (unsigned)(y0i * WW + x0i) * NGT + g;
        const unsigned i01 = mb + (unsigned)(y0i * WW + x1i) * NGT + g;
        const unsigned i10 = mb + (unsigned)(y1i * WW + x0i) * NGT + g;
        const unsigned i11 = mb + (unsigned)(y1i * WW + x1i) * NGT + g;
        const unsigned mode = g_maskflags;
        float v00, v01, v10, v11;
        if (mode & 4u) {
            const __nv_bfloat16* m = (const __nv_bfloat16*)masks;
            v00 = cvtf(m[i00]); v01 = cvtf(m[i01]); v10 = cvtf(m[i10]); v11 = cvtf(m[i11]);
        } else if (mode & 2u) {
            const float* m = (const float*)masks;
            v00 = m[i00]; v01 = m[i01]; v10 = m[i10]; v11 = m[i11];
        } else if (mode & 1u) {
            const unsigned char* m = (const unsigned char*)masks;
            v00 = cvtf(m[i00]); v01 = cvtf(m[i01]); v10 = cvtf(m[i10]); v11 = cvtf(m[i11]);
        } else {
            const int* m = (const int*)masks;
            v00 = cvtf(m[i00]); v01 = cvtf(m[i01]); v10 = cvtf(m[i10]); v11 = cvtf(m[i11]);
        }
        float val = (v00 * (1.0f - wx) + v01 * wx) * (1.0f - wy)
                  + (v10 * (1.0f - wx) + v11 * wx) * wy;
        const bool ok = (ys >= 0.0f) && (ys <= 511.0f) && (xs >= 0.0f) && (xs <= 511.0f);
        out[3600 + (size_t)(b * TR + j) * PIX + pp] = ok ? rintf(val) : 0.0f;  // half-even
    }

    // ---- row-k scalar outputs (overlaps gathers; tid 300 is never a gather thread) ----
    if (tid == 300) {
        float* ro = out + (size_t)(b * TR + k) * 4;
        float* cl = out + 1600 + (size_t)(b * TR + k);
        float* de = out + 2000 + (size_t)(b * TR + k) * 4;
        if (k < Np) {
            int n = sel200(s_cumP, s_bits, k, 0);
            int g = (int)(g_info[b][n] >> 2);
            float4 pv = ((const float4*)P)[n];
            float p0 = pv.x, p1 = pv.y, p2 = pv.z, p3 = pv.w;
            ro[0] = p0; ro[1] = p1; ro[2] = p2; ro[3] = p3;
            cl[0] = (float)s_cls[g];
            float h  = p2 - p0, w2 = p3 - p1;
            float cy = p0 + 0.5f * h, cx = p1 + 0.5f * w2;
            float g0 = s_gt[g][0], g1 = s_gt[g][1], g2 = s_gt[g][2], g3 = s_gt[g][3];
            float gh = g2 - g0, gw = g3 - g1;
            float gcy = g0 + 0.5f * gh, gcx = g1 + 0.5f * gw;
            de[0] = ((gcy - cy) / h)  / 0.1f;
            de[1] = ((gcx - cx) / w2) / 0.1f;
            de[2] = logf(gh / h)  / 0.2f;
            de[3] = logf(gw / w2) / 0.2f;
        } else if (k < Np + Nn) {
            int n = sel200(s_cumN, s_bits, k - Np, 1);
            float4 pv = ((const float4*)P)[n];
            ro[0] = pv.x; ro[1] = pv.y; ro[2] = pv.z; ro[3] = pv.w;
            cl[0] = 0.0f;
            de[0] = de[1] = de[2] = de[3] = 0.0f;
        } else {
            ro[0] = ro[1] = ro[2] = ro[3] = 0.0f;
            cl[0] = 0.0f;
            de[0] = de[1] = de[2] = de[3] = 0.0f;
        }
    }

    // ---- dead-row zeroing (tids >=320, overlaps gathers) ----
    if (tid >= 320 && k >= Np) {
        float* om = out + 3600 + (size_t)(b * TR + k) * PIX;
        for (int p = tid - 320; p < PIX; p += BT - 320) om[p] = 0.0f;
    }
}

// ---------------------------------------------------------------------------
extern "C" void kernel_launch(void* const* d_in, const int* in_sizes, int n_in,
                              void* d_out, int out_size)
{
    const float* props = (const float*)d_in[0];
    const int*   cls   = (const int*)  d_in[1];
    const float* gtb   = (const float*)d_in[2];
    const void*  masks = d_in[3];
    float* out = (float*)d_out;

    dtl_fused<<<NBLK, BT>>>(props, cls, gtb, masks, out);
}